// round 4
// baseline (speedup 1.0000x reference)
#include <cuda_runtime.h>
#include <math.h>

#define DT_F 0.1f
#define PAIRS_PER_BLOCK 256
#define MAX_BLOCKS 8192

__device__ double g_partials[MAX_BLOCKS];
__device__ unsigned int g_ticket = 0;   // reset by last block -> 0 at every replay start

__global__ void __launch_bounds__(256) fused_kernel(
    const float* __restrict__ para,
    const float* __restrict__ omega,
    const float* __restrict__ infd,
    float* __restrict__ out,
    int npairs, int ndata)
{
    __shared__ float4 s_om[PAIRS_PER_BLOCK * 5];   // 20 KB
    __shared__ double warp_sums[8];
    __shared__ bool s_is_last;

    // ---- scalar constants (redundant per block; 4 LDGs, free) ----
    float x00 = __ldg(para + 0), x01 = __ldg(para + 1);
    float x10 = __ldg(para + 2), x11 = __ldg(para + 3);
    float a    = 0.5f * (x00 - x11);
    float rez  = 0.5f + 0.5f * (x01 + x10);   // includes model coupling 0.5
    float imz  = 0.5f * (x01 - x10);
    float rsq  = a * a + rez * rez + imz * imz;
    float r    = sqrtf(fmaxf(rsq, 1e-30f));
    float c    = rez * rez;

    // ---- coalesced staging: block loads its 256-pair tile contiguously ----
    const int base_pair = blockIdx.x * PAIRS_PER_BLOCK;
    const int nvalid = min(PAIRS_PER_BLOCK, npairs - base_pair);
    const int nvec = nvalid * 5;
    const float4* gsrc = reinterpret_cast<const float4*>(omega) + (size_t)base_pair * 5;

    for (int i = threadIdx.x; i < nvec; i += blockDim.x)
        s_om[i] = gsrc[i];
    __syncthreads();

    // ---- per-pair compute from smem (LDS.128, 80B stride = conflict-free) ----
    double local = 0.0;
    if (threadIdx.x < nvalid) {
        const int t = threadIdx.x;
        float4 v0 = s_om[t * 5 + 0];
        float4 v1 = s_om[t * 5 + 1];
        float4 v2 = s_om[t * 5 + 2];
        float4 v3 = s_om[t * 5 + 3];
        float4 v4 = s_om[t * 5 + 4];
        float2 f  = reinterpret_cast<const float2*>(infd)[base_pair + t];

        float s0 = ((v0.x + v0.y) + (v0.z + v0.w))
                 + ((v1.x + v1.y) + (v1.z + v1.w))
                 + (v2.x + v2.y);
        float s1 = (v2.z + v2.w)
                 + ((v3.x + v3.y) + (v3.z + v3.w))
                 + ((v4.x + v4.y) + (v4.z + v4.w));

        {
            float phi   = DT_F * s0;
            float theta = phi * r;
            float sinc  = (rsq > 1e-24f) ? (sinf(theta) / r) : phi;
            float infid = 1.0f - sinc * sinc * c;
            float d     = f.x - infid;
            local += (double)(d * d);
        }
        {
            float phi   = DT_F * s1;
            float theta = phi * r;
            float sinc  = (rsq > 1e-24f) ? (sinf(theta) / r) : phi;
            float infid = 1.0f - sinc * sinc * c;
            float d     = f.y - infid;
            local += (double)(d * d);
        }
    }

    // ---- block reduction ----
    #pragma unroll
    for (int off = 16; off > 0; off >>= 1)
        local += __shfl_down_sync(0xFFFFFFFFu, local, off);

    int lane = threadIdx.x & 31;
    int wid  = threadIdx.x >> 5;
    if (lane == 0) warp_sums[wid] = local;
    __syncthreads();

    if (wid == 0) {
        double v = (lane < (blockDim.x >> 5)) ? warp_sums[lane] : 0.0;
        #pragma unroll
        for (int off = 4; off > 0; off >>= 1)
            v += __shfl_down_sync(0xFFFFFFFFu, v, off);
        if (lane == 0) {
            g_partials[blockIdx.x] = v;
            __threadfence();
            unsigned int tk = atomicAdd(&g_ticket, 1u);
            s_is_last = (tk == gridDim.x - 1);
        }
    }
    __syncthreads();

    // ---- last block finalizes ----
    if (s_is_last) {
        double v = 0.0;
        for (int i = threadIdx.x; i < gridDim.x; i += blockDim.x)
            v += g_partials[i];
        #pragma unroll
        for (int off = 16; off > 0; off >>= 1)
            v += __shfl_down_sync(0xFFFFFFFFu, v, off);
        if (lane == 0) warp_sums[wid] = v;
        __syncthreads();
        if (wid == 0) {
            double w = (lane < (blockDim.x >> 5)) ? warp_sums[lane] : 0.0;
            #pragma unroll
            for (int off = 4; off > 0; off >>= 1)
                w += __shfl_down_sync(0xFFFFFFFFu, w, off);
            if (lane == 0) {
                out[0] = (float)(w / (double)ndata);
                g_ticket = 0;   // clean state for next graph replay
            }
        }
    }
}

extern "C" void kernel_launch(void* const* d_in, const int* in_sizes, int n_in,
                              void* d_out, int out_size) {
    const float* para  = (const float*)d_in[0];
    const float* omega = (const float*)d_in[1];
    const float* infd  = (const float*)d_in[2];
    float* out = (float*)d_out;

    int ndata  = in_sizes[2];
    int npairs = ndata / 2;

    int threads = PAIRS_PER_BLOCK;
    int blocks  = (npairs + PAIRS_PER_BLOCK - 1) / PAIRS_PER_BLOCK;
    if (blocks > MAX_BLOCKS) blocks = MAX_BLOCKS;   // npairs=1M -> 3907, fits

    fused_kernel<<<blocks, threads>>>(para, omega, infd, out, npairs, ndata);
}

// round 6
// speedup vs baseline: 1.2764x; 1.2764x over previous
#include <cuda_runtime.h>
#include <math.h>

#define NQ_THREADS 256

__device__ double g_acc;               // running loss sum (reset by last block)
__device__ unsigned int g_ticket;      // reset by last block -> 0 each replay

__global__ void __launch_bounds__(NQ_THREADS) fused_kernel(
    const float* __restrict__ para,
    const float* __restrict__ omega,
    const float* __restrict__ infd,
    float* __restrict__ out,
    int nquads, int ndata)
{
    // ---- scalar constants (per-block recompute; 4 LDGs, trivial) ----
    float x00 = para[0], x01 = para[1], x10 = para[2], x11 = para[3];
    float a    = 0.5f * (x00 - x11);
    float rez  = 0.5f + 0.5f * (x01 + x10);       // model coupling 0.5 folded in
    float imz  = 0.5f * (x01 - x10);
    float rsq  = a * a + rez * rez + imz * imz;
    float c    = rez * rez;

    const int t = blockIdx.x * blockDim.x + threadIdx.x;

    float acc = 0.0f;
    if (t < nquads) {
        // 10 front-batched LDG.128 (omega rows 4t..4t+3) + 1 LDG.128 (infd)
        const float4* om = reinterpret_cast<const float4*>(omega) + (size_t)t * 10;
        float4 v0 = om[0]; float4 v1 = om[1]; float4 v2 = om[2];
        float4 v3 = om[3]; float4 v4 = om[4]; float4 v5 = om[5];
        float4 v6 = om[6]; float4 v7 = om[7]; float4 v8 = om[8];
        float4 v9 = om[9];
        float4 f = reinterpret_cast<const float4*>(infd)[t];

        float s0 = ((v0.x + v0.y) + (v0.z + v0.w))
                 + ((v1.x + v1.y) + (v1.z + v1.w)) + (v2.x + v2.y);
        float s1 = (v2.z + v2.w)
                 + ((v3.x + v3.y) + (v3.z + v3.w))
                 + ((v4.x + v4.y) + (v4.z + v4.w));
        float s2 = ((v5.x + v5.y) + (v5.z + v5.w))
                 + ((v6.x + v6.y) + (v6.z + v6.w)) + (v7.x + v7.y);
        float s3 = (v7.z + v7.w)
                 + ((v8.x + v8.y) + (v8.z + v8.w))
                 + ((v9.x + v9.y) + (v9.z + v9.w));

        // sinc = sin(phi*r)/r = phi*(1 - u/6 + u^2/120), u = rsq*phi^2  (|theta|<0.07)
        #define ROW(S, F)  do {                                            \
            float phi  = 0.1f * (S);                                      \
            float u    = rsq * (phi * phi);                               \
            float poly = fmaf(u, fmaf(u, (1.0f/120.0f), (-1.0f/6.0f)), 1.0f); \
            float sinc = phi * poly;                                      \
            float d    = ((F) - 1.0f) + sinc * sinc * c;                  \
            acc = fmaf(d, d, acc);                                        \
        } while (0)

        ROW(s0, f.x);
        ROW(s1, f.y);
        ROW(s2, f.z);
        ROW(s3, f.w);
        #undef ROW
    }

    // ---- float block reduction ----
    #pragma unroll
    for (int off = 16; off > 0; off >>= 1)
        acc += __shfl_down_sync(0xFFFFFFFFu, acc, off);

    __shared__ float warp_sums[NQ_THREADS / 32];
    __shared__ bool s_is_last;
    int lane = threadIdx.x & 31;
    int wid  = threadIdx.x >> 5;
    if (lane == 0) warp_sums[wid] = acc;
    __syncthreads();

    if (wid == 0) {
        float v = (lane < (NQ_THREADS / 32)) ? warp_sums[lane] : 0.0f;
        #pragma unroll
        for (int off = 4; off > 0; off >>= 1)
            v += __shfl_down_sync(0xFFFFFFFFu, v, off);
        if (lane == 0) {
            // release-add block sum into global accumulator (no full fence)
            asm volatile("red.release.gpu.global.add.f64 [%0], %1;"
                         :: "l"(&g_acc), "d"((double)v) : "memory");
            unsigned int tk;
            asm volatile("atom.acq_rel.gpu.global.add.u32 %0, [%1], %2;"
                         : "=r"(tk) : "l"(&g_ticket), "r"(1u) : "memory");
            s_is_last = (tk == gridDim.x - 1);
        }
    }
    __syncthreads();

    // ---- last block finalizes & resets state for the next graph replay ----
    if (s_is_last && threadIdx.x == 0) {
        double total;
        asm volatile("atom.acq_rel.gpu.global.add.f64 %0, [%1], %2;"
                     : "=d"(total) : "l"(&g_acc), "d"(0.0) : "memory");
        out[0] = (float)(total / (double)ndata);
        g_acc = 0.0;
        g_ticket = 0u;
    }
}

extern "C" void kernel_launch(void* const* d_in, const int* in_sizes, int n_in,
                              void* d_out, int out_size) {
    const float* para  = (const float*)d_in[0];
    const float* omega = (const float*)d_in[1];
    const float* infd  = (const float*)d_in[2];
    float* out = (float*)d_out;

    int ndata  = in_sizes[2];
    int nquads = ndata / 4;                       // 4 rows per thread

    int blocks = (nquads + NQ_THREADS - 1) / NQ_THREADS;   // 1954 for 2M rows
    fused_kernel<<<blocks, NQ_THREADS>>>(para, omega, infd, out, nquads, ndata);
}